// round 15
// baseline (speedup 1.0000x reference)
#include <cuda_runtime.h>
#include <cstdint>

#define BSZ 32
#define SEQ_LEN 4096
#define EMBED_DIM 1024
#define PAD_IDX 1
#define SEP_ID 4

// Scratch for computed positions (allocation-free rule: device global).
// Aligned for int4 loads in the gather.
__device__ __align__(16) int g_pos[BSZ * SEQ_LEN];

// ---------------------------------------------------------------------------
// Kernel 1: positions. One block per batch row, 1024 threads, 4 tokens/thread.
// pos[j] = (no PAD in [0..j]) ? (j - lastSepIdx<=j + 2) : 1
// dtype probe is warp-parallel (one lane-load + __any_sync vote, no barrier,
// no smem); speculative token loads for both layouts are issued first so all
// global latency overlaps. Triggers the dependent gather launch at the end.
// ---------------------------------------------------------------------------
__global__ __launch_bounds__(1024, 1)
void positions_kernel(const int* __restrict__ tok32) {
    const int row  = blockIdx.x;
    const int t    = threadIdx.x;            // 0..1023
    const int lane = t & 31;
    const int warp = t >> 5;

    __shared__ int s_fp[32];
    __shared__ int s_ls[32];

    const int base = t * 4;                  // local j within the row

    // ---- issue BOTH candidate token loads now (overlap with probe) ----
    const longlong2* p64 =
        (const longlong2*)((const long long*)tok32 + (size_t)row * SEQ_LEN + base);
    longlong2 a64 = __ldcs(&p64[0]);
    longlong2 b64 = __ldcs(&p64[1]);
    const int4* p32 = (const int4*)(tok32 + (size_t)row * SEQ_LEN + base);
    int4 a32 = __ldcs(&p32[0]);

    // ---- warp-parallel dtype probe (no barrier, no smem):
    // int64 tokens have zero high words for values < 2^31. Lane k inspects
    // odd word 2k+1; a single warp vote decides.
    int probe = __ldg(&tok32[2 * lane + 1]);
    const int is64 = !__any_sync(0xffffffffu, probe != 0);

    // ---- select the right interpretation ----
    int tk[4];
    if (is64) {
        tk[0] = (int)a64.x; tk[1] = (int)a64.y; tk[2] = (int)b64.x; tk[3] = (int)b64.y;
    } else {
        tk[0] = a32.x; tk[1] = a32.y; tk[2] = a32.z; tk[3] = a32.w;
    }

    // ---- local aggregate: fp = min PAD idx, ls = max SEP idx ----
    int fp = 0x7fffffff;
    int ls = 0;
    #pragma unroll
    for (int e = 0; e < 4; e++) {
        int j = base + e;
        if (tk[e] == PAD_IDX) fp = min(fp, j);
        if (tk[e] == SEP_ID)  ls = max(ls, j);
    }

    // ---- inclusive warp scan (min/max) ----
    int ifp = fp, ils = ls;
    #pragma unroll
    for (int d = 1; d < 32; d <<= 1) {
        int ofp = __shfl_up_sync(0xffffffffu, ifp, d);
        int ols = __shfl_up_sync(0xffffffffu, ils, d);
        if (lane >= d) { ifp = min(ifp, ofp); ils = max(ils, ols); }
    }
    if (lane == 31) { s_fp[warp] = ifp; s_ls[warp] = ils; }
    __syncthreads();

    // ---- scan warp aggregates (warp 0) ----
    if (warp == 0) {
        int wfp = s_fp[lane], wls = s_ls[lane];
        #pragma unroll
        for (int d = 1; d < 32; d <<= 1) {
            int ofp = __shfl_up_sync(0xffffffffu, wfp, d);
            int ols = __shfl_up_sync(0xffffffffu, wls, d);
            if (lane >= d) { wfp = min(wfp, ofp); wls = max(wls, ols); }
        }
        s_fp[lane] = wfp; s_ls[lane] = wls;
    }
    __syncthreads();

    // ---- exclusive prefix for this thread ----
    int exfp = 0x7fffffff, exls = 0;
    if (warp > 0) { exfp = s_fp[warp - 1]; exls = s_ls[warp - 1]; }
    int lfp = __shfl_up_sync(0xffffffffu, ifp, 1);
    int lls = __shfl_up_sync(0xffffffffu, ils, 1);
    if (lane > 0) { exfp = min(exfp, lfp); exls = max(exls, lls); }

    // ---- finalize my 4 elements ----
    int* out = g_pos + (size_t)row * SEQ_LEN;
    int fpx = exfp, lsx = exls;
    #pragma unroll
    for (int e = 0; e < 4; e++) {
        int j = base + e;
        if (tk[e] == PAD_IDX) fpx = min(fpx, j);
        if (tk[e] == SEP_ID)  lsx = max(lsx, j);
        out[j] = (j < fpx) ? (j - lsx + 2) : 1;
    }

    // PDL: allow the dependent gather grid to start launching now.
    cudaTriggerProgrammaticLaunchCompletion();
}

// ---------------------------------------------------------------------------
// Kernel 2: gather (converged best configuration, R12). 4 rows per block of
// 256 threads; thread t copies float4 column t of each row. Single LDG.128
// for the 4 position indices, then 4 independent LDG.128 (MLP=4) and 4
// STG.128 evict-first (__stcs) so the 512MB output stream doesn't evict the
// 16.8MB weights table from L2. Address math hoisted above the PDL wait.
// ---------------------------------------------------------------------------
#define ROWS_PER_BLK 4
#define F4_PER_ROW (EMBED_DIM / 4)   // 256

__global__ __launch_bounds__(256, 8)
void gather_kernel(const float4* __restrict__ w, float4* __restrict__ out) {
    // Address arithmetic independent of producer data — compute before wait.
    const int row0 = blockIdx.x * ROWS_PER_BLK;
    const int t    = threadIdx.x;
    const int4* pp = (const int4*)(g_pos + row0);
    float4* dst    = out + (size_t)row0 * F4_PER_ROW + t;

    // Hardware-backed wait for the positions grid (writes then visible).
    cudaGridDependencySynchronize();

    // One vectorized load for all 4 position indices (row0 % 4 == 0).
    const int4 p = *pp;

    float4 v0 = __ldg(w + (size_t)p.x * F4_PER_ROW + t);
    float4 v1 = __ldg(w + (size_t)p.y * F4_PER_ROW + t);
    float4 v2 = __ldg(w + (size_t)p.z * F4_PER_ROW + t);
    float4 v3 = __ldg(w + (size_t)p.w * F4_PER_ROW + t);

    __stcs(dst + 0 * F4_PER_ROW, v0);
    __stcs(dst + 1 * F4_PER_ROW, v1);
    __stcs(dst + 2 * F4_PER_ROW, v2);
    __stcs(dst + 3 * F4_PER_ROW, v3);
}

extern "C" void kernel_launch(void* const* d_in, const int* in_sizes, int n_in,
                              void* d_out, int out_size) {
    const int*   tokens  = (const int*)d_in[0];     // int32 or int64 (probed)
    const float* weights = (const float*)d_in[1];   // [4098, 1024] f32
    float* out = (float*)d_out;                     // [32, 4096, 1024] f32

    positions_kernel<<<BSZ, 1024>>>(tokens);

    // Gather launched with programmatic stream serialization (PDL): its blocks
    // may begin launching once positions_kernel triggers completion.
    cudaLaunchConfig_t cfg = {};
    cfg.gridDim  = dim3((BSZ * SEQ_LEN) / ROWS_PER_BLK, 1, 1);
    cfg.blockDim = dim3(256, 1, 1);
    cfg.dynamicSmemBytes = 0;
    cfg.stream = 0;

    cudaLaunchAttribute attrs[1];
    attrs[0].id = cudaLaunchAttributeProgrammaticStreamSerialization;
    attrs[0].val.programmaticStreamSerializationAllowed = 1;
    cfg.attrs = attrs;
    cfg.numAttrs = 1;

    cudaLaunchKernelEx(&cfg, gather_kernel,
                       (const float4*)weights, (float4*)out);
}

// round 16
// speedup vs baseline: 1.0096x; 1.0096x over previous
#include <cuda_runtime.h>
#include <cstdint>

#define BSZ 32
#define SEQ_LEN 4096
#define EMBED_DIM 1024
#define PAD_IDX 1
#define SEP_ID 4

// Scratch for computed positions (allocation-free rule: device global).
// Aligned for int4 loads in the gather.
__device__ __align__(16) int g_pos[BSZ * SEQ_LEN];

// ---------------------------------------------------------------------------
// Kernel 1: positions. One block per batch row, 1024 threads, 4 tokens/thread.
// pos[j] = (no PAD in [0..j]) ? (j - lastSepIdx<=j + 2) : 1
// dtype probe is warp-parallel (one lane-load + __any_sync vote, no barrier,
// no smem); speculative token loads for both layouts are issued first so all
// global latency overlaps. Triggers the dependent gather launch at the end.
// ---------------------------------------------------------------------------
__global__ __launch_bounds__(1024, 1)
void positions_kernel(const int* __restrict__ tok32) {
    const int row  = blockIdx.x;
    const int t    = threadIdx.x;            // 0..1023
    const int lane = t & 31;
    const int warp = t >> 5;

    __shared__ int s_fp[32];
    __shared__ int s_ls[32];

    const int base = t * 4;                  // local j within the row

    // ---- issue BOTH candidate token loads now (overlap with probe) ----
    const longlong2* p64 =
        (const longlong2*)((const long long*)tok32 + (size_t)row * SEQ_LEN + base);
    longlong2 a64 = __ldcs(&p64[0]);
    longlong2 b64 = __ldcs(&p64[1]);
    const int4* p32 = (const int4*)(tok32 + (size_t)row * SEQ_LEN + base);
    int4 a32 = __ldcs(&p32[0]);

    // ---- warp-parallel dtype probe (no barrier, no smem):
    // int64 tokens have zero high words for values < 2^31. Lane k inspects
    // odd word 2k+1; a single warp vote decides.
    int probe = __ldg(&tok32[2 * lane + 1]);
    const int is64 = !__any_sync(0xffffffffu, probe != 0);

    // ---- select the right interpretation ----
    int tk[4];
    if (is64) {
        tk[0] = (int)a64.x; tk[1] = (int)a64.y; tk[2] = (int)b64.x; tk[3] = (int)b64.y;
    } else {
        tk[0] = a32.x; tk[1] = a32.y; tk[2] = a32.z; tk[3] = a32.w;
    }

    // ---- local aggregate: fp = min PAD idx, ls = max SEP idx ----
    int fp = 0x7fffffff;
    int ls = 0;
    #pragma unroll
    for (int e = 0; e < 4; e++) {
        int j = base + e;
        if (tk[e] == PAD_IDX) fp = min(fp, j);
        if (tk[e] == SEP_ID)  ls = max(ls, j);
    }

    // ---- inclusive warp scan (min/max) ----
    int ifp = fp, ils = ls;
    #pragma unroll
    for (int d = 1; d < 32; d <<= 1) {
        int ofp = __shfl_up_sync(0xffffffffu, ifp, d);
        int ols = __shfl_up_sync(0xffffffffu, ils, d);
        if (lane >= d) { ifp = min(ifp, ofp); ils = max(ils, ols); }
    }
    if (lane == 31) { s_fp[warp] = ifp; s_ls[warp] = ils; }
    __syncthreads();

    // ---- scan warp aggregates (warp 0) ----
    if (warp == 0) {
        int wfp = s_fp[lane], wls = s_ls[lane];
        #pragma unroll
        for (int d = 1; d < 32; d <<= 1) {
            int ofp = __shfl_up_sync(0xffffffffu, wfp, d);
            int ols = __shfl_up_sync(0xffffffffu, wls, d);
            if (lane >= d) { wfp = min(wfp, ofp); wls = max(wls, ols); }
        }
        s_fp[lane] = wfp; s_ls[lane] = wls;
    }
    __syncthreads();

    // ---- exclusive prefix for this thread ----
    int exfp = 0x7fffffff, exls = 0;
    if (warp > 0) { exfp = s_fp[warp - 1]; exls = s_ls[warp - 1]; }
    int lfp = __shfl_up_sync(0xffffffffu, ifp, 1);
    int lls = __shfl_up_sync(0xffffffffu, ils, 1);
    if (lane > 0) { exfp = min(exfp, lfp); exls = max(exls, lls); }

    // ---- finalize my 4 elements ----
    int* out = g_pos + (size_t)row * SEQ_LEN;
    int fpx = exfp, lsx = exls;
    #pragma unroll
    for (int e = 0; e < 4; e++) {
        int j = base + e;
        if (tk[e] == PAD_IDX) fpx = min(fpx, j);
        if (tk[e] == SEP_ID)  lsx = max(lsx, j);
        out[j] = (j < fpx) ? (j - lsx + 2) : 1;
    }

    // PDL: allow the dependent gather grid to start launching now.
    cudaTriggerProgrammaticLaunchCompletion();
}

// ---------------------------------------------------------------------------
// Kernel 2: gather (converged best configuration). 4 rows per block of 256
// threads; thread t copies float4 column t of each row. Single LDG.128 for
// the 4 position indices, then 4 independent LDG.128 (MLP=4) and 4 STG.128
// evict-first (__stcs) so the 512MB output stream doesn't evict the 16.8MB
// weights table from L2. Opens with the PDL grid-dependency wait.
// At the HBM-write roofline: measured DRAM traffic ~= the output stream.
// ---------------------------------------------------------------------------
#define ROWS_PER_BLK 4
#define F4_PER_ROW (EMBED_DIM / 4)   // 256

__global__ __launch_bounds__(256, 8)
void gather_kernel(const float4* __restrict__ w, float4* __restrict__ out) {
    // Hardware-backed wait for the positions grid (writes then visible).
    cudaGridDependencySynchronize();

    const int row0 = blockIdx.x * ROWS_PER_BLK;
    const int t    = threadIdx.x;

    // One vectorized load for all 4 position indices (row0 % 4 == 0).
    const int4 p = *(const int4*)(g_pos + row0);

    float4 v0 = __ldg(w + (size_t)p.x * F4_PER_ROW + t);
    float4 v1 = __ldg(w + (size_t)p.y * F4_PER_ROW + t);
    float4 v2 = __ldg(w + (size_t)p.z * F4_PER_ROW + t);
    float4 v3 = __ldg(w + (size_t)p.w * F4_PER_ROW + t);

    float4* dst = out + (size_t)row0 * F4_PER_ROW + t;
    __stcs(dst + 0 * F4_PER_ROW, v0);
    __stcs(dst + 1 * F4_PER_ROW, v1);
    __stcs(dst + 2 * F4_PER_ROW, v2);
    __stcs(dst + 3 * F4_PER_ROW, v3);
}

extern "C" void kernel_launch(void* const* d_in, const int* in_sizes, int n_in,
                              void* d_out, int out_size) {
    const int*   tokens  = (const int*)d_in[0];     // int32 or int64 (probed)
    const float* weights = (const float*)d_in[1];   // [4098, 1024] f32
    float* out = (float*)d_out;                     // [32, 4096, 1024] f32

    positions_kernel<<<BSZ, 1024>>>(tokens);

    // Gather launched with programmatic stream serialization (PDL): its blocks
    // may begin launching once positions_kernel triggers completion.
    cudaLaunchConfig_t cfg = {};
    cfg.gridDim  = dim3((BSZ * SEQ_LEN) / ROWS_PER_BLK, 1, 1);
    cfg.blockDim = dim3(256, 1, 1);
    cfg.dynamicSmemBytes = 0;
    cfg.stream = 0;

    cudaLaunchAttribute attrs[1];
    attrs[0].id = cudaLaunchAttributeProgrammaticStreamSerialization;
    attrs[0].val.programmaticStreamSerializationAllowed = 1;
    cfg.attrs = attrs;
    cfg.numAttrs = 1;

    cudaLaunchKernelEx(&cfg, gather_kernel,
                       (const float4*)weights, (float4*)out);
}

// round 17
// speedup vs baseline: 1.0122x; 1.0025x over previous
#include <cuda_runtime.h>
#include <cstdint>

#define BSZ 32
#define SEQ_LEN 4096
#define EMBED_DIM 1024
#define PAD_IDX 1
#define SEP_ID 4

// Scratch for computed positions (allocation-free rule: device global).
// Aligned for int4 loads in the gather.
__device__ __align__(16) int g_pos[BSZ * SEQ_LEN];

// ---------------------------------------------------------------------------
// Kernel 1: positions. One block per batch row, 1024 threads, 4 tokens/thread.
// pos[j] = (no PAD in [0..j]) ? (j - lastSepIdx<=j + 2) : 1
// dtype probe is warp-parallel (one lane-load + __any_sync vote, no barrier,
// no smem); speculative token loads for both layouts are issued first so all
// global latency overlaps. Triggers the dependent gather launch at the end.
// ---------------------------------------------------------------------------
__global__ __launch_bounds__(1024, 1)
void positions_kernel(const int* __restrict__ tok32) {
    const int row  = blockIdx.x;
    const int t    = threadIdx.x;            // 0..1023
    const int lane = t & 31;
    const int warp = t >> 5;

    __shared__ int s_fp[32];
    __shared__ int s_ls[32];

    const int base = t * 4;                  // local j within the row

    // ---- issue BOTH candidate token loads now (overlap with probe) ----
    const longlong2* p64 =
        (const longlong2*)((const long long*)tok32 + (size_t)row * SEQ_LEN + base);
    longlong2 a64 = __ldcs(&p64[0]);
    longlong2 b64 = __ldcs(&p64[1]);
    const int4* p32 = (const int4*)(tok32 + (size_t)row * SEQ_LEN + base);
    int4 a32 = __ldcs(&p32[0]);

    // ---- warp-parallel dtype probe (no barrier, no smem):
    // int64 tokens have zero high words for values < 2^31. Lane k inspects
    // odd word 2k+1; a single warp vote decides.
    int probe = __ldg(&tok32[2 * lane + 1]);
    const int is64 = !__any_sync(0xffffffffu, probe != 0);

    // ---- select the right interpretation ----
    int tk[4];
    if (is64) {
        tk[0] = (int)a64.x; tk[1] = (int)a64.y; tk[2] = (int)b64.x; tk[3] = (int)b64.y;
    } else {
        tk[0] = a32.x; tk[1] = a32.y; tk[2] = a32.z; tk[3] = a32.w;
    }

    // ---- local aggregate: fp = min PAD idx, ls = max SEP idx ----
    int fp = 0x7fffffff;
    int ls = 0;
    #pragma unroll
    for (int e = 0; e < 4; e++) {
        int j = base + e;
        if (tk[e] == PAD_IDX) fp = min(fp, j);
        if (tk[e] == SEP_ID)  ls = max(ls, j);
    }

    // ---- inclusive warp scan (min/max) ----
    int ifp = fp, ils = ls;
    #pragma unroll
    for (int d = 1; d < 32; d <<= 1) {
        int ofp = __shfl_up_sync(0xffffffffu, ifp, d);
        int ols = __shfl_up_sync(0xffffffffu, ils, d);
        if (lane >= d) { ifp = min(ifp, ofp); ils = max(ils, ols); }
    }
    if (lane == 31) { s_fp[warp] = ifp; s_ls[warp] = ils; }
    __syncthreads();

    // ---- scan warp aggregates (warp 0) ----
    if (warp == 0) {
        int wfp = s_fp[lane], wls = s_ls[lane];
        #pragma unroll
        for (int d = 1; d < 32; d <<= 1) {
            int ofp = __shfl_up_sync(0xffffffffu, wfp, d);
            int ols = __shfl_up_sync(0xffffffffu, wls, d);
            if (lane >= d) { wfp = min(wfp, ofp); wls = max(wls, ols); }
        }
        s_fp[lane] = wfp; s_ls[lane] = wls;
    }
    __syncthreads();

    // ---- exclusive prefix for this thread ----
    int exfp = 0x7fffffff, exls = 0;
    if (warp > 0) { exfp = s_fp[warp - 1]; exls = s_ls[warp - 1]; }
    int lfp = __shfl_up_sync(0xffffffffu, ifp, 1);
    int lls = __shfl_up_sync(0xffffffffu, ils, 1);
    if (lane > 0) { exfp = min(exfp, lfp); exls = max(exls, lls); }

    // ---- finalize my 4 elements ----
    int* out = g_pos + (size_t)row * SEQ_LEN;
    int fpx = exfp, lsx = exls;
    #pragma unroll
    for (int e = 0; e < 4; e++) {
        int j = base + e;
        if (tk[e] == PAD_IDX) fpx = min(fpx, j);
        if (tk[e] == SEP_ID)  lsx = max(lsx, j);
        out[j] = (j < fpx) ? (j - lsx + 2) : 1;
    }

    // PDL: allow the dependent gather grid to start launching now.
    cudaTriggerProgrammaticLaunchCompletion();
}

// ---------------------------------------------------------------------------
// Kernel 2: gather (converged best configuration — FINAL). 4 rows per block
// of 256 threads; thread t copies float4 column t of each row. Single
// LDG.128 for the 4 position indices, then 4 independent LDG.128 (MLP=4)
// and 4 STG.128 evict-first (__stcs) so the 512MB output stream doesn't
// evict the 16.8MB weights table from L2. Opens with the PDL wait.
// At the HBM-write roofline: measured DRAM traffic == the output stream.
// ---------------------------------------------------------------------------
#define ROWS_PER_BLK 4
#define F4_PER_ROW (EMBED_DIM / 4)   // 256

__global__ __launch_bounds__(256, 8)
void gather_kernel(const float4* __restrict__ w, float4* __restrict__ out) {
    // Hardware-backed wait for the positions grid (writes then visible).
    cudaGridDependencySynchronize();

    const int row0 = blockIdx.x * ROWS_PER_BLK;
    const int t    = threadIdx.x;

    // One vectorized load for all 4 position indices (row0 % 4 == 0).
    const int4 p = *(const int4*)(g_pos + row0);

    float4 v0 = __ldg(w + (size_t)p.x * F4_PER_ROW + t);
    float4 v1 = __ldg(w + (size_t)p.y * F4_PER_ROW + t);
    float4 v2 = __ldg(w + (size_t)p.z * F4_PER_ROW + t);
    float4 v3 = __ldg(w + (size_t)p.w * F4_PER_ROW + t);

    float4* dst = out + (size_t)row0 * F4_PER_ROW + t;
    __stcs(dst + 0 * F4_PER_ROW, v0);
    __stcs(dst + 1 * F4_PER_ROW, v1);
    __stcs(dst + 2 * F4_PER_ROW, v2);
    __stcs(dst + 3 * F4_PER_ROW, v3);
}

extern "C" void kernel_launch(void* const* d_in, const int* in_sizes, int n_in,
                              void* d_out, int out_size) {
    const int*   tokens  = (const int*)d_in[0];     // int32 or int64 (probed)
    const float* weights = (const float*)d_in[1];   // [4098, 1024] f32
    float* out = (float*)d_out;                     // [32, 4096, 1024] f32

    positions_kernel<<<BSZ, 1024>>>(tokens);

    // Gather launched with programmatic stream serialization (PDL): its blocks
    // may begin launching once positions_kernel triggers completion.
    cudaLaunchConfig_t cfg = {};
    cfg.gridDim  = dim3((BSZ * SEQ_LEN) / ROWS_PER_BLK, 1, 1);
    cfg.blockDim = dim3(256, 1, 1);
    cfg.dynamicSmemBytes = 0;
    cfg.stream = 0;

    cudaLaunchAttribute attrs[1];
    attrs[0].id = cudaLaunchAttributeProgrammaticStreamSerialization;
    attrs[0].val.programmaticStreamSerializationAllowed = 1;
    cfg.attrs = attrs;
    cfg.numAttrs = 1;

    cudaLaunchKernelEx(&cfg, gather_kernel,
                       (const float4*)weights, (float4*)out);
}